// round 13
// baseline (speedup 1.0000x reference)
#include <cuda_runtime.h>
#include <cstdint>
#include <cstdio>

#define N_ATOMS   32768
#define NFEAT     7584
#define HIDDEN    256
#define NSPECIES  4
// 8192 atoms per species -> species = row >> 13

// ---------------- scratch (static device arrays: allocation-free) ----------
__device__ float g_h1[(size_t)N_ATOMS * HIDDEN];
__device__ float g_h2[(size_t)N_ATOMS * HIDDEN];

// ---------------- PTX helpers ----------------------------------------------
__device__ __forceinline__ uint32_t f2tf32(float x) {
    uint32_t r;
    asm volatile("cvt.rna.tf32.f32 %0, %1;\n" : "=r"(r) : "f"(x));
    return r;
}

__device__ __forceinline__ void mma_tf32(float& d0, float& d1, float& d2, float& d3,
                                         uint32_t a0, uint32_t a1, uint32_t a2, uint32_t a3,
                                         uint32_t b0, uint32_t b1) {
    asm volatile(
        "mma.sync.aligned.m16n8k8.row.col.f32.tf32.tf32.f32 "
        "{%0,%1,%2,%3}, {%4,%5,%6,%7}, {%8,%9}, {%0,%1,%2,%3};\n"
        : "+f"(d0), "+f"(d1), "+f"(d2), "+f"(d3)
        : "r"(a0), "r"(a1), "r"(a2), "r"(a3), "r"(b0), "r"(b1));
}

#define CP_ASYNC16(sm_u32, gptr) \
    asm volatile("cp.async.cg.shared.global [%0], [%1], 16;\n" :: "r"(sm_u32), "l"(gptr))
#define CP_COMMIT() asm volatile("cp.async.commit_group;\n" ::: "memory")
#define CP_WAIT1()  asm volatile("cp.async.wait_group 1;\n" ::: "memory")
#define CP_WAIT0()  asm volatile("cp.async.wait_group 0;\n" ::: "memory")

// ---------------- tiled TF32 GEMM + bias + SiLU -----------------------------
// C[32768, 256] = silu(A[32768, K] @ W[species, K, 256] + b[species, 256])
// BM=128, BN=128, BK=32. 256 threads = 8 warps in 2(m) x 4(n); warp tile 64x32.
// A smem [128][36] (stride 36 -> conflict-free A-frag LDS)
// B smem [32][136]  (stride 136 -> conflict-free B-frag LDS)
#define A_STRIDE 36
#define B_STRIDE 136
#define A_STAGE  (128 * A_STRIDE)   // 4608 floats
#define B_STAGE  (32 * B_STRIDE)    // 4352 floats
#define SMEM_FLOATS (2 * (A_STAGE + B_STAGE))
#define SMEM_BYTES  (SMEM_FLOATS * 4)

template <int K>
__global__ void __launch_bounds__(256)
gemm_bias_silu(const float* __restrict__ A, const float* __restrict__ W,
               const float* __restrict__ bias, float* __restrict__ C)
{
    extern __shared__ float sm[];
    float* As = sm;                  // [2][A_STAGE]
    float* Bs = sm + 2 * A_STAGE;    // [2][B_STAGE]

    const int tid   = threadIdx.x;
    const int mBase = blockIdx.y * 128;
    const int n0    = blockIdx.x * 128;
    const int sp    = mBase >> 13;                    // species
    const float* Wp = W + (size_t)sp * K * HIDDEN;

    const uint32_t as_base = (uint32_t)__cvta_generic_to_shared(As);
    const uint32_t bs_base = (uint32_t)__cvta_generic_to_shared(Bs);

    auto load_stage = [&](int st, int k0) {
        // A tile: 128 rows x 32 floats = 1024 float4 chunks
        #pragma unroll
        for (int i = 0; i < 4; i++) {
            int ch = tid + i * 256;
            int r  = ch >> 3;
            int c4 = (ch & 7) << 2;
            const float* g = A + (size_t)(mBase + r) * K + k0 + c4;
            CP_ASYNC16(as_base + (uint32_t)(st * A_STAGE + r * A_STRIDE + c4) * 4u, g);
        }
        // B tile: 32 rows x 128 floats = 1024 float4 chunks
        #pragma unroll
        for (int i = 0; i < 4; i++) {
            int ch = tid + i * 256;
            int r  = ch >> 5;
            int c4 = (ch & 31) << 2;
            const float* g = Wp + (size_t)(k0 + r) * HIDDEN + n0 + c4;
            CP_ASYNC16(bs_base + (uint32_t)(st * B_STAGE + r * B_STRIDE + c4) * 4u, g);
        }
    };

    float acc[4][4][4];
    #pragma unroll
    for (int i = 0; i < 4; i++)
        #pragma unroll
        for (int j = 0; j < 4; j++)
            #pragma unroll
            for (int c = 0; c < 4; c++) acc[i][j][c] = 0.f;

    const int lane = tid & 31, wid = tid >> 5;
    const int wm = wid & 1;       // 0..1 (m)
    const int wn = wid >> 1;      // 0..3 (n)
    const int gr = lane >> 2;     // groupID 0..7
    const int tg = lane & 3;      // thread-in-group 0..3

    constexpr int KT = K / 32;

    load_stage(0, 0);
    CP_COMMIT();

    for (int kt = 0; kt < KT; ++kt) {
        if (kt + 1 < KT) load_stage((kt + 1) & 1, (kt + 1) * 32);
        CP_COMMIT();
        CP_WAIT1();
        __syncthreads();

        const float* a_s = As + (kt & 1) * A_STAGE;
        const float* b_s = Bs + (kt & 1) * B_STAGE;

        #pragma unroll
        for (int kk = 0; kk < 4; ++kk) {
            uint32_t af[4][4];
            #pragma unroll
            for (int mi = 0; mi < 4; mi++) {
                const int rb = wm * 64 + mi * 16;
                const float* p = a_s + (rb + gr) * A_STRIDE + kk * 8 + tg;
                af[mi][0] = f2tf32(p[0]);                  // (row,   k)
                af[mi][1] = f2tf32(p[8 * A_STRIDE]);       // (row+8, k)
                af[mi][2] = f2tf32(p[4]);                  // (row,   k+4)
                af[mi][3] = f2tf32(p[8 * A_STRIDE + 4]);   // (row+8, k+4)
            }
            uint32_t bf[4][2];
            #pragma unroll
            for (int ni = 0; ni < 4; ni++) {
                const int nb = wn * 32 + ni * 8;
                const float* p = b_s + (kk * 8 + tg) * B_STRIDE + nb + gr;
                bf[ni][0] = f2tf32(p[0]);                  // (k,   n)
                bf[ni][1] = f2tf32(p[4 * B_STRIDE]);       // (k+4, n)
            }
            #pragma unroll
            for (int mi = 0; mi < 4; mi++)
                #pragma unroll
                for (int ni = 0; ni < 4; ni++)
                    mma_tf32(acc[mi][ni][0], acc[mi][ni][1], acc[mi][ni][2], acc[mi][ni][3],
                             af[mi][0], af[mi][1], af[mi][2], af[mi][3],
                             bf[ni][0], bf[ni][1]);
        }
        __syncthreads();
    }
    CP_WAIT0();

    // epilogue: bias + SiLU, write float2 pairs
    const float* bp = bias + sp * HIDDEN;
    #pragma unroll
    for (int ni = 0; ni < 4; ni++) {
        const int col = n0 + wn * 32 + ni * 8 + tg * 2;
        const float bv0 = bp[col], bv1 = bp[col + 1];
        #pragma unroll
        for (int mi = 0; mi < 4; mi++) {
            const int row = mBase + wm * 64 + mi * 16 + gr;
            float x0 = acc[mi][ni][0] + bv0;
            float x1 = acc[mi][ni][1] + bv1;
            float x2 = acc[mi][ni][2] + bv0;
            float x3 = acc[mi][ni][3] + bv1;
            x0 = x0 / (1.f + __expf(-x0));
            x1 = x1 / (1.f + __expf(-x1));
            x2 = x2 / (1.f + __expf(-x2));
            x3 = x3 / (1.f + __expf(-x3));
            *(float2*)(C + (size_t)row * HIDDEN + col)       = make_float2(x0, x1);
            *(float2*)(C + (size_t)(row + 8) * HIDDEN + col) = make_float2(x2, x3);
        }
    }
}

// ---------------- layer 4 + segment-sum ------------------------------------
// One warp per atom: dot(h[atom], W4[sp]) + b4[sp] -> atomicAdd(out[struct])
__global__ void __launch_bounds__(256)
final_reduce(const float* __restrict__ H, const float* __restrict__ W4,
             const float* __restrict__ b4, const int* __restrict__ sidx,
             float* __restrict__ out)
{
    const int atom = blockIdx.x * 8 + (threadIdx.x >> 5);
    const int lane = threadIdx.x & 31;
    const int sp   = atom >> 13;

    const float4* h = (const float4*)(H + (size_t)atom * HIDDEN);
    const float4* w = (const float4*)(W4 + (size_t)sp * HIDDEN);

    float sum = 0.f;
    #pragma unroll
    for (int i = 0; i < 2; i++) {
        float4 hv = h[lane + i * 32];
        float4 wv = w[lane + i * 32];
        sum += hv.x * wv.x + hv.y * wv.y + hv.z * wv.z + hv.w * wv.w;
    }
    #pragma unroll
    for (int o = 16; o; o >>= 1) sum += __shfl_xor_sync(0xFFFFFFFFu, sum, o);

    if (lane == 0) atomicAdd(&out[sidx[atom]], sum + b4[sp]);
}

// ---------------- launch ----------------------------------------------------
extern "C" void kernel_launch(void* const* d_in, const int* in_sizes, int n_in,
                              void* d_out, int out_size)
{
    // Inputs in reference order, skipping scalar (size-1) entries like
    // n_structures: features, structure_index, W1, b1, W2, b2, W3, b3, W4, b4
    const void* q[10];
    int pi = 0;
    for (int i = 0; i < n_in && pi < 10; i++) {
        if (in_sizes[i] == 1) continue;
        q[pi++] = d_in[i];
    }
    const float* feat = (const float*)q[0];
    const int*   sidx = (const int*)  q[1];
    const float* W1   = (const float*)q[2];
    const float* b1   = (const float*)q[3];
    const float* W2   = (const float*)q[4];
    const float* b2   = (const float*)q[5];
    const float* W3   = (const float*)q[6];
    const float* b3   = (const float*)q[7];
    const float* W4   = (const float*)q[8];
    const float* b4   = (const float*)q[9];
    float* out = (float*)d_out;

    void *p1 = nullptr, *p2 = nullptr;
    cudaGetSymbolAddress(&p1, g_h1);
    cudaGetSymbolAddress(&p2, g_h2);
    float* h1 = (float*)p1;
    float* h2 = (float*)p2;

    cudaFuncSetAttribute((const void*)gemm_bias_silu<NFEAT>,
                         cudaFuncAttributeMaxDynamicSharedMemorySize, SMEM_BYTES);
    cudaFuncSetAttribute((const void*)gemm_bias_silu<HIDDEN>,
                         cudaFuncAttributeMaxDynamicSharedMemorySize, SMEM_BYTES);

    cudaMemsetAsync(d_out, 0, (size_t)out_size * sizeof(float));

    dim3 grid(HIDDEN / 128, N_ATOMS / 128);   // (2, 256)
    dim3 blk(256);

    gemm_bias_silu<NFEAT> <<<grid, blk, SMEM_BYTES>>>(feat, W1, b1, h1);
    gemm_bias_silu<HIDDEN><<<grid, blk, SMEM_BYTES>>>(h1,   W2, b2, h2);
    gemm_bias_silu<HIDDEN><<<grid, blk, SMEM_BYTES>>>(h2,   W3, b3, h1);
    final_reduce<<<N_ATOMS / 8, 256>>>(h1, W4, b4, sidx, out);
}

// round 14
// speedup vs baseline: 1.0010x; 1.0010x over previous
#include <cuda_runtime.h>
#include <cstdint>
#include <cstdio>

#define N_ATOMS   32768
#define NFEAT     7584
#define HIDDEN    256
#define NSPECIES  4
// 8192 atoms per species -> species = row >> 13

// ---------------- scratch (static device arrays: allocation-free) ----------
__device__ float g_h1[(size_t)N_ATOMS * HIDDEN];
__device__ float g_h2[(size_t)N_ATOMS * HIDDEN];

// ---------------- PTX helpers ----------------------------------------------
__device__ __forceinline__ uint32_t f2tf32(float x) {
    uint32_t r;
    asm volatile("cvt.rna.tf32.f32 %0, %1;\n" : "=r"(r) : "f"(x));
    return r;
}

__device__ __forceinline__ void mma_tf32(float& d0, float& d1, float& d2, float& d3,
                                         uint32_t a0, uint32_t a1, uint32_t a2, uint32_t a3,
                                         uint32_t b0, uint32_t b1) {
    asm volatile(
        "mma.sync.aligned.m16n8k8.row.col.f32.tf32.tf32.f32 "
        "{%0,%1,%2,%3}, {%4,%5,%6,%7}, {%8,%9}, {%0,%1,%2,%3};\n"
        : "+f"(d0), "+f"(d1), "+f"(d2), "+f"(d3)
        : "r"(a0), "r"(a1), "r"(a2), "r"(a3), "r"(b0), "r"(b1));
}

#define CP_ASYNC16(sm_u32, gptr) \
    asm volatile("cp.async.cg.shared.global [%0], [%1], 16;\n" :: "r"(sm_u32), "l"(gptr))
#define CP_COMMIT() asm volatile("cp.async.commit_group;\n" ::: "memory")
#define CP_WAIT1()  asm volatile("cp.async.wait_group 1;\n" ::: "memory")
#define CP_WAIT0()  asm volatile("cp.async.wait_group 0;\n" ::: "memory")

// ---------------- tiled TF32 GEMM + bias + SiLU -----------------------------
// C[32768, 256] = silu(A[32768, K] @ W[species, K, 256] + b[species, 256])
// BM=128, BN=128, BK=32. 256 threads = 8 warps in 2(m) x 4(n); warp tile 64x32.
// A smem [128][36] (stride 36 -> conflict-free A-frag LDS)
// B smem [32][136]  (stride 136 -> conflict-free B-frag LDS)
#define A_STRIDE 36
#define B_STRIDE 136
#define A_STAGE  (128 * A_STRIDE)   // 4608 floats
#define B_STAGE  (32 * B_STRIDE)    // 4352 floats
#define SMEM_FLOATS (2 * (A_STAGE + B_STAGE))
#define SMEM_BYTES  (SMEM_FLOATS * 4)

template <int K>
__global__ void __launch_bounds__(256)
gemm_bias_silu(const float* __restrict__ A, const float* __restrict__ W,
               const float* __restrict__ bias, float* __restrict__ C)
{
    extern __shared__ float sm[];
    float* As = sm;                  // [2][A_STAGE]
    float* Bs = sm + 2 * A_STAGE;    // [2][B_STAGE]

    const int tid   = threadIdx.x;
    const int mBase = blockIdx.y * 128;
    const int n0    = blockIdx.x * 128;
    const int sp    = mBase >> 13;                    // species
    const float* Wp = W + (size_t)sp * K * HIDDEN;

    const uint32_t as_base = (uint32_t)__cvta_generic_to_shared(As);
    const uint32_t bs_base = (uint32_t)__cvta_generic_to_shared(Bs);

    auto load_stage = [&](int st, int k0) {
        // A tile: 128 rows x 32 floats = 1024 float4 chunks
        #pragma unroll
        for (int i = 0; i < 4; i++) {
            int ch = tid + i * 256;
            int r  = ch >> 3;
            int c4 = (ch & 7) << 2;
            const float* g = A + (size_t)(mBase + r) * K + k0 + c4;
            CP_ASYNC16(as_base + (uint32_t)(st * A_STAGE + r * A_STRIDE + c4) * 4u, g);
        }
        // B tile: 32 rows x 128 floats = 1024 float4 chunks
        #pragma unroll
        for (int i = 0; i < 4; i++) {
            int ch = tid + i * 256;
            int r  = ch >> 5;
            int c4 = (ch & 31) << 2;
            const float* g = Wp + (size_t)(k0 + r) * HIDDEN + n0 + c4;
            CP_ASYNC16(bs_base + (uint32_t)(st * B_STAGE + r * B_STRIDE + c4) * 4u, g);
        }
    };

    float acc[4][4][4];
    #pragma unroll
    for (int i = 0; i < 4; i++)
        #pragma unroll
        for (int j = 0; j < 4; j++)
            #pragma unroll
            for (int c = 0; c < 4; c++) acc[i][j][c] = 0.f;

    const int lane = tid & 31, wid = tid >> 5;
    const int wm = wid & 1;       // 0..1 (m)
    const int wn = wid >> 1;      // 0..3 (n)
    const int gr = lane >> 2;     // groupID 0..7
    const int tg = lane & 3;      // thread-in-group 0..3

    constexpr int KT = K / 32;

    load_stage(0, 0);
    CP_COMMIT();

    for (int kt = 0; kt < KT; ++kt) {
        if (kt + 1 < KT) load_stage((kt + 1) & 1, (kt + 1) * 32);
        CP_COMMIT();
        CP_WAIT1();
        __syncthreads();

        const float* a_s = As + (kt & 1) * A_STAGE;
        const float* b_s = Bs + (kt & 1) * B_STAGE;

        #pragma unroll
        for (int kk = 0; kk < 4; ++kk) {
            uint32_t af[4][4];
            #pragma unroll
            for (int mi = 0; mi < 4; mi++) {
                const int rb = wm * 64 + mi * 16;
                const float* p = a_s + (rb + gr) * A_STRIDE + kk * 8 + tg;
                af[mi][0] = f2tf32(p[0]);                  // (row,   k)
                af[mi][1] = f2tf32(p[8 * A_STRIDE]);       // (row+8, k)
                af[mi][2] = f2tf32(p[4]);                  // (row,   k+4)
                af[mi][3] = f2tf32(p[8 * A_STRIDE + 4]);   // (row+8, k+4)
            }
            uint32_t bf[4][2];
            #pragma unroll
            for (int ni = 0; ni < 4; ni++) {
                const int nb = wn * 32 + ni * 8;
                const float* p = b_s + (kk * 8 + tg) * B_STRIDE + nb + gr;
                bf[ni][0] = f2tf32(p[0]);                  // (k,   n)
                bf[ni][1] = f2tf32(p[4 * B_STRIDE]);       // (k+4, n)
            }
            #pragma unroll
            for (int mi = 0; mi < 4; mi++)
                #pragma unroll
                for (int ni = 0; ni < 4; ni++)
                    mma_tf32(acc[mi][ni][0], acc[mi][ni][1], acc[mi][ni][2], acc[mi][ni][3],
                             af[mi][0], af[mi][1], af[mi][2], af[mi][3],
                             bf[ni][0], bf[ni][1]);
        }
        __syncthreads();
    }
    CP_WAIT0();

    // epilogue: bias + SiLU, write float2 pairs
    const float* bp = bias + sp * HIDDEN;
    #pragma unroll
    for (int ni = 0; ni < 4; ni++) {
        const int col = n0 + wn * 32 + ni * 8 + tg * 2;
        const float bv0 = bp[col], bv1 = bp[col + 1];
        #pragma unroll
        for (int mi = 0; mi < 4; mi++) {
            const int row = mBase + wm * 64 + mi * 16 + gr;
            float x0 = acc[mi][ni][0] + bv0;
            float x1 = acc[mi][ni][1] + bv1;
            float x2 = acc[mi][ni][2] + bv0;
            float x3 = acc[mi][ni][3] + bv1;
            x0 = x0 / (1.f + __expf(-x0));
            x1 = x1 / (1.f + __expf(-x1));
            x2 = x2 / (1.f + __expf(-x2));
            x3 = x3 / (1.f + __expf(-x3));
            *(float2*)(C + (size_t)row * HIDDEN + col)       = make_float2(x0, x1);
            *(float2*)(C + (size_t)(row + 8) * HIDDEN + col) = make_float2(x2, x3);
        }
    }
}

// ---------------- layer 4 + segment-sum ------------------------------------
// One warp per atom: dot(h[atom], W4[sp]) + b4[sp] -> atomicAdd(out[struct])
__global__ void __launch_bounds__(256)
final_reduce(const float* __restrict__ H, const float* __restrict__ W4,
             const float* __restrict__ b4, const int* __restrict__ sidx,
             float* __restrict__ out)
{
    const int atom = blockIdx.x * 8 + (threadIdx.x >> 5);
    const int lane = threadIdx.x & 31;
    const int sp   = atom >> 13;

    const float4* h = (const float4*)(H + (size_t)atom * HIDDEN);
    const float4* w = (const float4*)(W4 + (size_t)sp * HIDDEN);

    float sum = 0.f;
    #pragma unroll
    for (int i = 0; i < 2; i++) {
        float4 hv = h[lane + i * 32];
        float4 wv = w[lane + i * 32];
        sum += hv.x * wv.x + hv.y * wv.y + hv.z * wv.z + hv.w * wv.w;
    }
    #pragma unroll
    for (int o = 16; o; o >>= 1) sum += __shfl_xor_sync(0xFFFFFFFFu, sum, o);

    if (lane == 0) atomicAdd(&out[sidx[atom]], sum + b4[sp]);
}

// ---------------- launch ----------------------------------------------------
extern "C" void kernel_launch(void* const* d_in, const int* in_sizes, int n_in,
                              void* d_out, int out_size)
{
    // Inputs in reference order, skipping scalar (size-1) entries like
    // n_structures: features, structure_index, W1, b1, W2, b2, W3, b3, W4, b4
    const void* q[10];
    int pi = 0;
    for (int i = 0; i < n_in && pi < 10; i++) {
        if (in_sizes[i] == 1) continue;
        q[pi++] = d_in[i];
    }
    const float* feat = (const float*)q[0];
    const int*   sidx = (const int*)  q[1];
    const float* W1   = (const float*)q[2];
    const float* b1   = (const float*)q[3];
    const float* W2   = (const float*)q[4];
    const float* b2   = (const float*)q[5];
    const float* W3   = (const float*)q[6];
    const float* b3   = (const float*)q[7];
    const float* W4   = (const float*)q[8];
    const float* b4   = (const float*)q[9];
    float* out = (float*)d_out;

    void *p1 = nullptr, *p2 = nullptr;
    cudaGetSymbolAddress(&p1, g_h1);
    cudaGetSymbolAddress(&p2, g_h2);
    float* h1 = (float*)p1;
    float* h2 = (float*)p2;

    cudaFuncSetAttribute((const void*)gemm_bias_silu<NFEAT>,
                         cudaFuncAttributeMaxDynamicSharedMemorySize, SMEM_BYTES);
    cudaFuncSetAttribute((const void*)gemm_bias_silu<HIDDEN>,
                         cudaFuncAttributeMaxDynamicSharedMemorySize, SMEM_BYTES);

    cudaMemsetAsync(d_out, 0, (size_t)out_size * sizeof(float));

    dim3 grid(HIDDEN / 128, N_ATOMS / 128);   // (2, 256)
    dim3 blk(256);

    gemm_bias_silu<NFEAT> <<<grid, blk, SMEM_BYTES>>>(feat, W1, b1, h1);
    gemm_bias_silu<HIDDEN><<<grid, blk, SMEM_BYTES>>>(h1,   W2, b2, h2);
    gemm_bias_silu<HIDDEN><<<grid, blk, SMEM_BYTES>>>(h2,   W3, b3, h1);
    final_reduce<<<N_ATOMS / 8, 256>>>(h1, W4, b4, sidx, out);
}

// round 15
// speedup vs baseline: 1.0020x; 1.0011x over previous
#include <cuda_runtime.h>
#include <cstdint>
#include <cstdio>

#define N_ATOMS   32768
#define NFEAT     7584
#define HIDDEN    256
#define NSPECIES  4
// 8192 atoms per species -> species = row >> 13

// ---------------- scratch (static device arrays: allocation-free) ----------
__device__ float g_h1[(size_t)N_ATOMS * HIDDEN];
__device__ float g_h2[(size_t)N_ATOMS * HIDDEN];

// ---------------- PTX helpers ----------------------------------------------
__device__ __forceinline__ uint32_t f2tf32(float x) {
    uint32_t r;
    asm volatile("cvt.rna.tf32.f32 %0, %1;\n" : "=r"(r) : "f"(x));
    return r;
}

__device__ __forceinline__ void mma_tf32(float& d0, float& d1, float& d2, float& d3,
                                         uint32_t a0, uint32_t a1, uint32_t a2, uint32_t a3,
                                         uint32_t b0, uint32_t b1) {
    asm volatile(
        "mma.sync.aligned.m16n8k8.row.col.f32.tf32.tf32.f32 "
        "{%0,%1,%2,%3}, {%4,%5,%6,%7}, {%8,%9}, {%0,%1,%2,%3};\n"
        : "+f"(d0), "+f"(d1), "+f"(d2), "+f"(d3)
        : "r"(a0), "r"(a1), "r"(a2), "r"(a3), "r"(b0), "r"(b1));
}

#define CP_ASYNC16(sm_u32, gptr) \
    asm volatile("cp.async.cg.shared.global [%0], [%1], 16;\n" :: "r"(sm_u32), "l"(gptr))
#define CP_COMMIT() asm volatile("cp.async.commit_group;\n" ::: "memory")
#define CP_WAIT1()  asm volatile("cp.async.wait_group 1;\n" ::: "memory")
#define CP_WAIT0()  asm volatile("cp.async.wait_group 0;\n" ::: "memory")

// ---------------- tiled TF32 GEMM + bias + SiLU -----------------------------
// C[32768, 256] = silu(A[32768, K] @ W[species, K, 256] + b[species, 256])
// BM=128, BN=128, BK=32. 256 threads = 8 warps in 2(m) x 4(n); warp tile 64x32.
// A smem [128][36] (stride 36 -> conflict-free A-frag LDS)
// B smem [32][136]  (stride 136 -> conflict-free B-frag LDS)
#define A_STRIDE 36
#define B_STRIDE 136
#define A_STAGE  (128 * A_STRIDE)   // 4608 floats
#define B_STAGE  (32 * B_STRIDE)    // 4352 floats
#define SMEM_FLOATS (2 * (A_STAGE + B_STAGE))
#define SMEM_BYTES  (SMEM_FLOATS * 4)

template <int K>
__global__ void __launch_bounds__(256)
gemm_bias_silu(const float* __restrict__ A, const float* __restrict__ W,
               const float* __restrict__ bias, float* __restrict__ C)
{
    extern __shared__ float sm[];
    float* As = sm;                  // [2][A_STAGE]
    float* Bs = sm + 2 * A_STAGE;    // [2][B_STAGE]

    const int tid   = threadIdx.x;
    const int mBase = blockIdx.y * 128;
    const int n0    = blockIdx.x * 128;
    const int sp    = mBase >> 13;                    // species
    const float* Wp = W + (size_t)sp * K * HIDDEN;

    const uint32_t as_base = (uint32_t)__cvta_generic_to_shared(As);
    const uint32_t bs_base = (uint32_t)__cvta_generic_to_shared(Bs);

    auto load_stage = [&](int st, int k0) {
        // A tile: 128 rows x 32 floats = 1024 float4 chunks
        #pragma unroll
        for (int i = 0; i < 4; i++) {
            int ch = tid + i * 256;
            int r  = ch >> 3;
            int c4 = (ch & 7) << 2;
            const float* g = A + (size_t)(mBase + r) * K + k0 + c4;
            CP_ASYNC16(as_base + (uint32_t)(st * A_STAGE + r * A_STRIDE + c4) * 4u, g);
        }
        // B tile: 32 rows x 128 floats = 1024 float4 chunks
        #pragma unroll
        for (int i = 0; i < 4; i++) {
            int ch = tid + i * 256;
            int r  = ch >> 5;
            int c4 = (ch & 31) << 2;
            const float* g = Wp + (size_t)(k0 + r) * HIDDEN + n0 + c4;
            CP_ASYNC16(bs_base + (uint32_t)(st * B_STAGE + r * B_STRIDE + c4) * 4u, g);
        }
    };

    float acc[4][4][4];
    #pragma unroll
    for (int i = 0; i < 4; i++)
        #pragma unroll
        for (int j = 0; j < 4; j++)
            #pragma unroll
            for (int c = 0; c < 4; c++) acc[i][j][c] = 0.f;

    const int lane = tid & 31, wid = tid >> 5;
    const int wm = wid & 1;       // 0..1 (m)
    const int wn = wid >> 1;      // 0..3 (n)
    const int gr = lane >> 2;     // groupID 0..7
    const int tg = lane & 3;      // thread-in-group 0..3

    constexpr int KT = K / 32;

    load_stage(0, 0);
    CP_COMMIT();

    for (int kt = 0; kt < KT; ++kt) {
        if (kt + 1 < KT) load_stage((kt + 1) & 1, (kt + 1) * 32);
        CP_COMMIT();
        CP_WAIT1();
        __syncthreads();

        const float* a_s = As + (kt & 1) * A_STAGE;
        const float* b_s = Bs + (kt & 1) * B_STAGE;

        #pragma unroll
        for (int kk = 0; kk < 4; ++kk) {
            uint32_t af[4][4];
            #pragma unroll
            for (int mi = 0; mi < 4; mi++) {
                const int rb = wm * 64 + mi * 16;
                const float* p = a_s + (rb + gr) * A_STRIDE + kk * 8 + tg;
                af[mi][0] = f2tf32(p[0]);                  // (row,   k)
                af[mi][1] = f2tf32(p[8 * A_STRIDE]);       // (row+8, k)
                af[mi][2] = f2tf32(p[4]);                  // (row,   k+4)
                af[mi][3] = f2tf32(p[8 * A_STRIDE + 4]);   // (row+8, k+4)
            }
            uint32_t bf[4][2];
            #pragma unroll
            for (int ni = 0; ni < 4; ni++) {
                const int nb = wn * 32 + ni * 8;
                const float* p = b_s + (kk * 8 + tg) * B_STRIDE + nb + gr;
                bf[ni][0] = f2tf32(p[0]);                  // (k,   n)
                bf[ni][1] = f2tf32(p[4 * B_STRIDE]);       // (k+4, n)
            }
            #pragma unroll
            for (int mi = 0; mi < 4; mi++)
                #pragma unroll
                for (int ni = 0; ni < 4; ni++)
                    mma_tf32(acc[mi][ni][0], acc[mi][ni][1], acc[mi][ni][2], acc[mi][ni][3],
                             af[mi][0], af[mi][1], af[mi][2], af[mi][3],
                             bf[ni][0], bf[ni][1]);
        }
        __syncthreads();
    }
    CP_WAIT0();

    // epilogue: bias + SiLU, write float2 pairs
    const float* bp = bias + sp * HIDDEN;
    #pragma unroll
    for (int ni = 0; ni < 4; ni++) {
        const int col = n0 + wn * 32 + ni * 8 + tg * 2;
        const float bv0 = bp[col], bv1 = bp[col + 1];
        #pragma unroll
        for (int mi = 0; mi < 4; mi++) {
            const int row = mBase + wm * 64 + mi * 16 + gr;
            float x0 = acc[mi][ni][0] + bv0;
            float x1 = acc[mi][ni][1] + bv1;
            float x2 = acc[mi][ni][2] + bv0;
            float x3 = acc[mi][ni][3] + bv1;
            x0 = x0 / (1.f + __expf(-x0));
            x1 = x1 / (1.f + __expf(-x1));
            x2 = x2 / (1.f + __expf(-x2));
            x3 = x3 / (1.f + __expf(-x3));
            *(float2*)(C + (size_t)row * HIDDEN + col)       = make_float2(x0, x1);
            *(float2*)(C + (size_t)(row + 8) * HIDDEN + col) = make_float2(x2, x3);
        }
    }
}

// ---------------- layer 4 + segment-sum ------------------------------------
// One warp per atom: dot(h[atom], W4[sp]) + b4[sp] -> atomicAdd(out[struct])
__global__ void __launch_bounds__(256)
final_reduce(const float* __restrict__ H, const float* __restrict__ W4,
             const float* __restrict__ b4, const int* __restrict__ sidx,
             float* __restrict__ out)
{
    const int atom = blockIdx.x * 8 + (threadIdx.x >> 5);
    const int lane = threadIdx.x & 31;
    const int sp   = atom >> 13;

    const float4* h = (const float4*)(H + (size_t)atom * HIDDEN);
    const float4* w = (const float4*)(W4 + (size_t)sp * HIDDEN);

    float sum = 0.f;
    #pragma unroll
    for (int i = 0; i < 2; i++) {
        float4 hv = h[lane + i * 32];
        float4 wv = w[lane + i * 32];
        sum += hv.x * wv.x + hv.y * wv.y + hv.z * wv.z + hv.w * wv.w;
    }
    #pragma unroll
    for (int o = 16; o; o >>= 1) sum += __shfl_xor_sync(0xFFFFFFFFu, sum, o);

    if (lane == 0) atomicAdd(&out[sidx[atom]], sum + b4[sp]);
}

// ---------------- launch ----------------------------------------------------
extern "C" void kernel_launch(void* const* d_in, const int* in_sizes, int n_in,
                              void* d_out, int out_size)
{
    // Inputs in reference order, skipping scalar (size-1) entries like
    // n_structures: features, structure_index, W1, b1, W2, b2, W3, b3, W4, b4
    const void* q[10];
    int pi = 0;
    for (int i = 0; i < n_in && pi < 10; i++) {
        if (in_sizes[i] == 1) continue;
        q[pi++] = d_in[i];
    }
    const float* feat = (const float*)q[0];
    const int*   sidx = (const int*)  q[1];
    const float* W1   = (const float*)q[2];
    const float* b1   = (const float*)q[3];
    const float* W2   = (const float*)q[4];
    const float* b2   = (const float*)q[5];
    const float* W3   = (const float*)q[6];
    const float* b3   = (const float*)q[7];
    const float* W4   = (const float*)q[8];
    const float* b4   = (const float*)q[9];
    float* out = (float*)d_out;

    void *p1 = nullptr, *p2 = nullptr;
    cudaGetSymbolAddress(&p1, g_h1);
    cudaGetSymbolAddress(&p2, g_h2);
    float* h1 = (float*)p1;
    float* h2 = (float*)p2;

    cudaFuncSetAttribute((const void*)gemm_bias_silu<NFEAT>,
                         cudaFuncAttributeMaxDynamicSharedMemorySize, SMEM_BYTES);
    cudaFuncSetAttribute((const void*)gemm_bias_silu<HIDDEN>,
                         cudaFuncAttributeMaxDynamicSharedMemorySize, SMEM_BYTES);

    cudaMemsetAsync(d_out, 0, (size_t)out_size * sizeof(float));

    dim3 grid(HIDDEN / 128, N_ATOMS / 128);   // (2, 256)
    dim3 blk(256);

    gemm_bias_silu<NFEAT> <<<grid, blk, SMEM_BYTES>>>(feat, W1, b1, h1);
    gemm_bias_silu<HIDDEN><<<grid, blk, SMEM_BYTES>>>(h1,   W2, b2, h2);
    gemm_bias_silu<HIDDEN><<<grid, blk, SMEM_BYTES>>>(h2,   W3, b3, h1);
    final_reduce<<<N_ATOMS / 8, 256>>>(h1, W4, b4, sidx, out);
}